// round 1
// baseline (speedup 1.0000x reference)
#include <cuda_runtime.h>
#include <cstdint>

// Problem shape (fixed for this dataset entry)
#define BB 8
#define CC 16
#define HH 512
#define WW 512
#define HWP (HH * WW)           // 262144 pixels per batch
#define NPIX (BB * HWP)         // 2,097,152 total pixels

// Channel-last scratch accumulator: [B, HW, C] so the 16 channels of one
// target pixel are contiguous (64B) -> enables red.global.add.v4.f32.
// Static __device__ array: no runtime allocation (allocation guards safe).
__device__ float g_scratch[(size_t)BB * HWP * CC];

// ---------------------------------------------------------------------------
// Splat: one thread per source pixel. Reads flow (coalesced float2), the 16
// channel values (coalesced per-channel across the warp), computes the 4
// bilinear corners, and issues 4x red.v4 per valid corner into the
// channel-last scratch.
// ---------------------------------------------------------------------------
__global__ void __launch_bounds__(256) splat_kernel(
    const float* __restrict__ im0,   // [B, C, H, W]
    const float* __restrict__ flow)  // [B, H, W, 2]
{
    int idx = blockIdx.x * blockDim.x + threadIdx.x;
    if (idx >= NPIX) return;

    int b = idx / HWP;
    int p = idx - b * HWP;
    int h = p / WW;
    int w = p - h * WW;

    float2 f = reinterpret_cast<const float2*>(flow)[idx];
    float x = (float)w + f.x;
    float y = (float)h + f.y;

    float x0f = floorf(x);
    float y0f = floorf(y);
    int   x0  = (int)x0f;
    int   y0  = (int)y0f;
    float fx  = x - x0f;
    float fy  = y - y0f;

    float w00 = (1.0f - fx) * (1.0f - fy);  // (x0, y0)  NW
    float w01 = fx * (1.0f - fy);           // (x1, y0)  NE
    float w10 = (1.0f - fx) * fy;           // (x0, y1)  SW
    float w11 = fx * fy;                    // (x1, y1)  SE

    // Gather the 16 channel values for this pixel (stride HW between channels;
    // coalesced across the warp for each channel).
    float v[CC];
    const float* src = im0 + (size_t)b * CC * HWP + p;
#pragma unroll
    for (int c = 0; c < CC; c++) v[c] = src[(size_t)c * HWP];

    float* sbase = g_scratch + (size_t)b * HWP * CC;

    auto splat_corner = [&](int xi, int yi, float wgt) {
        if (xi < 0 || xi >= WW || yi < 0 || yi >= HH) return;
        if (wgt == 0.0f) return;  // exact-zero weight contributes nothing
        float* dst = sbase + ((size_t)(yi * WW + xi)) * CC;
#pragma unroll
        for (int g = 0; g < 4; g++) {
            float a0 = v[4 * g + 0] * wgt;
            float a1 = v[4 * g + 1] * wgt;
            float a2 = v[4 * g + 2] * wgt;
            float a3 = v[4 * g + 3] * wgt;
            asm volatile(
                "red.global.add.v4.f32 [%0], {%1, %2, %3, %4};"
                :: "l"(dst + 4 * g), "f"(a0), "f"(a1), "f"(a2), "f"(a3)
                : "memory");
        }
    };

    splat_corner(x0,     y0,     w00);
    splat_corner(x0 + 1, y0,     w01);
    splat_corner(x0,     y0 + 1, w10);
    splat_corner(x0 + 1, y0 + 1, w11);
}

// ---------------------------------------------------------------------------
// Transpose: scratch [B, HW, C] -> out [B, C, HW].
// Each thread owns one pixel: 4x ld.128 (warp covers a contiguous 2KB span,
// all sectors consumed via L1) then 16 coalesced per-channel stores.
// Writes EVERY output element, so no separate d_out init is needed.
// ---------------------------------------------------------------------------
__global__ void __launch_bounds__(256) transpose_kernel(float* __restrict__ out)
{
    int idx = blockIdx.x * blockDim.x + threadIdx.x;
    if (idx >= NPIX) return;

    int b = idx / HWP;
    int p = idx - b * HWP;

    const float4* src = reinterpret_cast<const float4*>(g_scratch + (size_t)idx * CC);
    float4 r0 = src[0];
    float4 r1 = src[1];
    float4 r2 = src[2];
    float4 r3 = src[3];

    float* dst = out + (size_t)b * CC * HWP + p;
    dst[(size_t)0  * HWP] = r0.x;
    dst[(size_t)1  * HWP] = r0.y;
    dst[(size_t)2  * HWP] = r0.z;
    dst[(size_t)3  * HWP] = r0.w;
    dst[(size_t)4  * HWP] = r1.x;
    dst[(size_t)5  * HWP] = r1.y;
    dst[(size_t)6  * HWP] = r1.z;
    dst[(size_t)7  * HWP] = r1.w;
    dst[(size_t)8  * HWP] = r2.x;
    dst[(size_t)9  * HWP] = r2.y;
    dst[(size_t)10 * HWP] = r2.z;
    dst[(size_t)11 * HWP] = r2.w;
    dst[(size_t)12 * HWP] = r3.x;
    dst[(size_t)13 * HWP] = r3.y;
    dst[(size_t)14 * HWP] = r3.z;
    dst[(size_t)15 * HWP] = r3.w;
}

extern "C" void kernel_launch(void* const* d_in, const int* in_sizes, int n_in,
                              void* d_out, int out_size)
{
    // Identify inputs by size (im0 = B*C*H*W, flow = B*H*W*2) to be robust to
    // metadata ordering.
    const float* im0;
    const float* flow;
    if (in_sizes[0] == BB * CC * HWP) {
        im0  = (const float*)d_in[0];
        flow = (const float*)d_in[1];
    } else {
        im0  = (const float*)d_in[1];
        flow = (const float*)d_in[0];
    }
    float* out = (float*)d_out;

    void* sptr = nullptr;
    cudaGetSymbolAddress(&sptr, g_scratch);

    // 1) Zero the accumulator (captured as a memset node).
    cudaMemsetAsync(sptr, 0, (size_t)BB * HWP * CC * sizeof(float), 0);

    // 2) Splat with v4 vector atomics.
    int threads = 256;
    int blocks  = (NPIX + threads - 1) / threads;
    splat_kernel<<<blocks, threads>>>(im0, flow);

    // 3) Transpose to the required [B, C, H, W] layout.
    transpose_kernel<<<blocks, threads>>>(out);
}